// round 1
// baseline (speedup 1.0000x reference)
#include <cuda_runtime.h>
#include <cuda_bf16.h>

// Implicit-GEMM 3x3 conv, fp32 SGEMM-style.
// GEMM view: Out[p][oc] = sum_k A[p][k] * W2d[oc][k]
//   p  = ((n*56+oh)*56+ow), M = 100352 (= 784 * 128 exactly)
//   oc = output channel,    N = 256    (= 2 * 128 exactly)
//   k  = c*9 + r*3 + s,     K = 2304   (= 288 * 8 exactly)
// W in OIHW is already row-major [256][2304] in k.

#define CONV_N   32
#define CONV_C   256
#define CONV_HW  56
#define CONV_PIX (CONV_HW * CONV_HW)      // 3136
#define CONV_K   256
#define GEMM_K   (CONV_C * 9)             // 2304

#define TM 128
#define TN 128
#define TK 8
#define BS_PITCH (TN + 4)                 // 132: bank = (4k + oc) % 32, conflict-free

__global__ __launch_bounds__(256, 2)
void conv3x3_igemm_kernel(const float* __restrict__ x,
                          const float* __restrict__ w,
                          float* __restrict__ out) {
    __shared__ float As[TK][TM];          // k-major A tile (im2col pixels)
    __shared__ float Bs[TK][BS_PITCH];    // k-major B tile (weights)

    const int tid     = threadIdx.x;
    const int block_m = blockIdx.x * TM;  // pixel base
    const int block_n = blockIdx.y * TN;  // oc base

    // ---- A loader mapping: tile 8k x 128p; 256 threads -> 2 k-rows per pass, 4 passes
    const int a_p  = tid & 127;           // pixel within tile (coalesced dim)
    const int a_k0 = tid >> 7;            // 0..1
    const int p_glob_a = block_m + a_p;
    const int n_a  = p_glob_a / CONV_PIX;
    const int hw_a = p_glob_a - n_a * CONV_PIX;
    const int oh_a = hw_a / CONV_HW;
    const int ow_a = hw_a - oh_a * CONV_HW;
    const float* x_n = x + (size_t)n_a * CONV_C * CONV_PIX;

    // ---- B loader mapping: tile 8k x 128oc; thread: k = tid%8, oc = tid/8, 4 passes
    const int b_k   = tid & 7;
    const int b_oc0 = tid >> 3;           // 0..31

    // ---- compute mapping: tx -> pixel octet (contiguous!), ty -> oc octet
    const int tx = tid & 15;
    const int ty = tid >> 4;

    float acc[8][8];                      // [oc][pix]
    #pragma unroll
    for (int i = 0; i < 8; i++)
        #pragma unroll
        for (int j = 0; j < 8; j++) acc[i][j] = 0.f;

    float a_reg[4], b_reg[4];

    // prologue: fetch tile 0
    #pragma unroll
    for (int i = 0; i < 4; i++) {
        const int k = a_k0 + i * 2;       // kt = 0
        const int c  = k / 9;
        const int rs = k - c * 9;
        const int r  = rs / 3;
        const int s  = rs - r * 3;
        const int ih = oh_a + r - 1, iw = ow_a + s - 1;
        const bool ok = ((unsigned)ih < CONV_HW) && ((unsigned)iw < CONV_HW);
        a_reg[i] = ok ? __ldg(&x_n[(c * CONV_HW + ih) * CONV_HW + iw]) : 0.f;
    }
    #pragma unroll
    for (int i = 0; i < 4; i++) {
        const int oc = block_n + b_oc0 + i * 32;
        b_reg[i] = __ldg(&w[(size_t)oc * GEMM_K + b_k]);
    }
    #pragma unroll
    for (int i = 0; i < 4; i++) As[a_k0 + i * 2][a_p] = a_reg[i];
    #pragma unroll
    for (int i = 0; i < 4; i++) Bs[b_k][b_oc0 + i * 32] = b_reg[i];
    __syncthreads();

    for (int kt = 0; kt < GEMM_K; kt += TK) {
        const bool more = (kt + TK) < GEMM_K;
        if (more) {
            // prefetch next tile into registers while smem tile is consumed
            #pragma unroll
            for (int i = 0; i < 4; i++) {
                const int k = kt + TK + a_k0 + i * 2;
                const int c  = k / 9;
                const int rs = k - c * 9;
                const int r  = rs / 3;
                const int s  = rs - r * 3;
                const int ih = oh_a + r - 1, iw = ow_a + s - 1;
                const bool ok = ((unsigned)ih < CONV_HW) && ((unsigned)iw < CONV_HW);
                a_reg[i] = ok ? __ldg(&x_n[(c * CONV_HW + ih) * CONV_HW + iw]) : 0.f;
            }
            #pragma unroll
            for (int i = 0; i < 4; i++) {
                const int oc = block_n + b_oc0 + i * 32;
                b_reg[i] = __ldg(&w[(size_t)oc * GEMM_K + kt + TK + b_k]);
            }
        }

        // compute this stage
        #pragma unroll
        for (int kk = 0; kk < TK; kk++) {
            float a[8], b[8];
            const float4 a0 = *(const float4*)&As[kk][tx * 8];
            const float4 a1 = *(const float4*)&As[kk][tx * 8 + 4];
            const float4 b0 = *(const float4*)&Bs[kk][ty * 8];
            const float4 b1 = *(const float4*)&Bs[kk][ty * 8 + 4];
            a[0]=a0.x; a[1]=a0.y; a[2]=a0.z; a[3]=a0.w;
            a[4]=a1.x; a[5]=a1.y; a[6]=a1.z; a[7]=a1.w;
            b[0]=b0.x; b[1]=b0.y; b[2]=b0.z; b[3]=b0.w;
            b[4]=b1.x; b[5]=b1.y; b[6]=b1.z; b[7]=b1.w;
            #pragma unroll
            for (int i = 0; i < 8; i++)
                #pragma unroll
                for (int j = 0; j < 8; j++)
                    acc[i][j] = fmaf(b[i], a[j], acc[i][j]);
        }
        __syncthreads();
        if (more) {
            #pragma unroll
            for (int i = 0; i < 4; i++) As[a_k0 + i * 2][a_p] = a_reg[i];
            #pragma unroll
            for (int i = 0; i < 4; i++) Bs[b_k][b_oc0 + i * 32] = b_reg[i];
            __syncthreads();
        }
    }

    // ---- epilogue: coalesced float4 stores (pixel octet is contiguous, never
    // crosses an n-boundary since 3136 % 8 == 0)
    const int p0 = block_m + tx * 8;
    const int n  = p0 / CONV_PIX;
    const int hw = p0 - n * CONV_PIX;
    float* outp = out + (size_t)n * CONV_K * CONV_PIX + hw;
    const int oc0 = block_n + ty * 8;
    #pragma unroll
    for (int i = 0; i < 8; i++) {
        float* o = outp + (size_t)(oc0 + i) * CONV_PIX;
        *(float4*)(o)     = make_float4(acc[i][0], acc[i][1], acc[i][2], acc[i][3]);
        *(float4*)(o + 4) = make_float4(acc[i][4], acc[i][5], acc[i][6], acc[i][7]);
    }
}

extern "C" void kernel_launch(void* const* d_in, const int* in_sizes, int n_in,
                              void* d_out, int out_size) {
    const float* x = (const float*)d_in[0];   // [32,256,56,56]
    const float* w = (const float*)d_in[1];   // [256,256,3,3] == [256][2304]
    float* out = (float*)d_out;               // [32,256,56,56]

    dim3 grid( (CONV_N * CONV_PIX) / TM,      // 784
               CONV_K / TN );                 // 2
    conv3x3_igemm_kernel<<<grid, 256>>>(x, w, out);
}

// round 2
// speedup vs baseline: 1.0705x; 1.0705x over previous
#include <cuda_runtime.h>
#include <cuda_bf16.h>
#include <cstdint>

// Implicit-GEMM 3x3 conv, fp32, using packed f32x2 FMA (Blackwell FFMA2).
// GEMM view: Out[p][oc] = sum_k A[p][k] * W2d[oc][k]
//   p  = ((n*56+oh)*56+ow), M = 100352 (= 784 * 128)
//   oc = output channel,    N = 256    (= 2 * 128)
//   k  = c*9 + r*3 + s,     K = 2304   (= 288 * 8)
// W in OIHW is already row-major [256][2304] in k.

#define CONV_N   32
#define CONV_C   256
#define CONV_HW  56
#define CONV_PIX (CONV_HW * CONV_HW)      // 3136
#define CONV_K   256
#define GEMM_K   (CONV_C * 9)             // 2304

#define TM 128
#define TN 128
#define TK 8
#define BS_PITCH (TN + 4)                 // 132: conflict-free

// packed fp32x2 FMA: d = a*b + c (per 32-bit lane), SASS FFMA2
__device__ __forceinline__ void ffma2(unsigned long long& d,
                                      unsigned long long a,
                                      unsigned long long b) {
    asm("fma.rn.f32x2 %0, %1, %2, %0;" : "+l"(d) : "l"(a), "l"(b));
}
__device__ __forceinline__ unsigned long long bcast2(float v) {
    unsigned long long r;
    asm("mov.b64 %0, {%1, %1};" : "=l"(r) : "f"(v));
    return r;
}

__global__ __launch_bounds__(256, 2)
void conv3x3_igemm_kernel(const float* __restrict__ x,
                          const float* __restrict__ w,
                          float* __restrict__ out) {
    __shared__ float As[TK][TM];          // k-major A tile (im2col pixels)
    __shared__ float Bs[TK][BS_PITCH];    // k-major B tile (weights)

    const int tid     = threadIdx.x;
    const int block_m = blockIdx.x * TM;  // pixel base
    const int block_n = blockIdx.y * TN;  // oc base

    // ---- A loader: tile 8k x 128p; 256 threads -> 2 k-rows per pass, 4 passes
    const int a_p  = tid & 127;
    const int a_k0 = tid >> 7;            // 0..1
    const int p_glob_a = block_m + a_p;
    const int n_a  = p_glob_a / CONV_PIX;
    const int hw_a = p_glob_a - n_a * CONV_PIX;
    const int oh_a = hw_a / CONV_HW;
    const int ow_a = hw_a - oh_a * CONV_HW;
    const float* x_n = x + (size_t)n_a * CONV_C * CONV_PIX;

    // ---- B loader: k = tid%8, oc = tid/8, 4 passes
    const int b_k   = tid & 7;
    const int b_oc0 = tid >> 3;

    // ---- compute mapping: tx -> pixel octet (contiguous), ty -> oc octet
    const int tx = tid & 15;
    const int ty = tid >> 4;

    // acc2[i][j]: oc i, pixel pair j (pixels 2j, 2j+1 in low/high lanes)
    unsigned long long acc2[8][4];
    #pragma unroll
    for (int i = 0; i < 8; i++)
        #pragma unroll
        for (int j = 0; j < 4; j++) acc2[i][j] = 0ull;

    float a_reg[4], b_reg[4];

    // prologue: fetch tile 0
    #pragma unroll
    for (int i = 0; i < 4; i++) {
        const int k = a_k0 + i * 2;
        const int c  = k / 9;
        const int rs = k - c * 9;
        const int r  = rs / 3;
        const int s  = rs - r * 3;
        const int ih = oh_a + r - 1, iw = ow_a + s - 1;
        const bool ok = ((unsigned)ih < CONV_HW) && ((unsigned)iw < CONV_HW);
        a_reg[i] = ok ? __ldg(&x_n[(c * CONV_HW + ih) * CONV_HW + iw]) : 0.f;
    }
    #pragma unroll
    for (int i = 0; i < 4; i++) {
        const int oc = block_n + b_oc0 + i * 32;
        b_reg[i] = __ldg(&w[(size_t)oc * GEMM_K + b_k]);
    }
    #pragma unroll
    for (int i = 0; i < 4; i++) As[a_k0 + i * 2][a_p] = a_reg[i];
    #pragma unroll
    for (int i = 0; i < 4; i++) Bs[b_k][b_oc0 + i * 32] = b_reg[i];
    __syncthreads();

    for (int kt = 0; kt < GEMM_K; kt += TK) {
        const bool more = (kt + TK) < GEMM_K;
        if (more) {
            // prefetch next tile into registers while smem tile is consumed
            #pragma unroll
            for (int i = 0; i < 4; i++) {
                const int k = kt + TK + a_k0 + i * 2;
                const int c  = k / 9;
                const int rs = k - c * 9;
                const int r  = rs / 3;
                const int s  = rs - r * 3;
                const int ih = oh_a + r - 1, iw = ow_a + s - 1;
                const bool ok = ((unsigned)ih < CONV_HW) && ((unsigned)iw < CONV_HW);
                a_reg[i] = ok ? __ldg(&x_n[(c * CONV_HW + ih) * CONV_HW + iw]) : 0.f;
            }
            #pragma unroll
            for (int i = 0; i < 4; i++) {
                const int oc = block_n + b_oc0 + i * 32;
                b_reg[i] = __ldg(&w[(size_t)oc * GEMM_K + kt + TK + b_k]);
            }
        }

        // compute this stage: 32 FFMA2 per k-step instead of 64 FFMA
        #pragma unroll
        for (int kk = 0; kk < TK; kk++) {
            // A pixel octet as 4 packed pairs (32B-aligned)
            const unsigned long long* aR =
                reinterpret_cast<const unsigned long long*>(&As[kk][tx * 8]);
            unsigned long long a2[4];
            #pragma unroll
            for (int j = 0; j < 4; j++) a2[j] = aR[j];

            const float4 b0 = *(const float4*)&Bs[kk][ty * 8];
            const float4 b1 = *(const float4*)&Bs[kk][ty * 8 + 4];
            float b[8];
            b[0]=b0.x; b[1]=b0.y; b[2]=b0.z; b[3]=b0.w;
            b[4]=b1.x; b[5]=b1.y; b[6]=b1.z; b[7]=b1.w;

            #pragma unroll
            for (int i = 0; i < 8; i++) {
                const unsigned long long bb = bcast2(b[i]);
                #pragma unroll
                for (int j = 0; j < 4; j++)
                    ffma2(acc2[i][j], bb, a2[j]);
            }
        }
        __syncthreads();
        if (more) {
            #pragma unroll
            for (int i = 0; i < 4; i++) As[a_k0 + i * 2][a_p] = a_reg[i];
            #pragma unroll
            for (int i = 0; i < 4; i++) Bs[b_k][b_oc0 + i * 32] = b_reg[i];
            __syncthreads();
        }
    }

    // ---- epilogue: unpack pairs, coalesced float4 stores
    const int p0 = block_m + tx * 8;
    const int n  = p0 / CONV_PIX;
    const int hw = p0 - n * CONV_PIX;
    float* outp = out + (size_t)n * CONV_K * CONV_PIX + hw;
    const int oc0 = block_n + ty * 8;
    #pragma unroll
    for (int i = 0; i < 8; i++) {
        float v[8];
        #pragma unroll
        for (int j = 0; j < 4; j++) {
            asm("mov.b64 {%0, %1}, %2;"
                : "=f"(v[2*j]), "=f"(v[2*j+1]) : "l"(acc2[i][j]));
        }
        float* o = outp + (size_t)(oc0 + i) * CONV_PIX;
        *(float4*)(o)     = make_float4(v[0], v[1], v[2], v[3]);
        *(float4*)(o + 4) = make_float4(v[4], v[5], v[6], v[7]);
    }
}

extern "C" void kernel_launch(void* const* d_in, const int* in_sizes, int n_in,
                              void* d_out, int out_size) {
    const float* x = (const float*)d_in[0];   // [32,256,56,56]
    const float* w = (const float*)d_in[1];   // [256,256,3,3] == [256][2304]
    float* out = (float*)d_out;               // [32,256,56,56]

    dim3 grid( (CONV_N * CONV_PIX) / TM,      // 784
               CONV_K / TN );                 // 2
    conv3x3_igemm_kernel<<<grid, 256>>>(x, w, out);
}

// round 3
// speedup vs baseline: 1.1880x; 1.1098x over previous
#include <cuda_runtime.h>
#include <cuda_bf16.h>
#include <cstdint>

// Implicit-GEMM 3x3 conv, fp32, packed f32x2 FMA (FFMA2), double-buffered smem.
// GEMM view: Out[p][oc] = sum_k A[p][k] * W2d[oc][k]
//   p  = ((n*56+oh)*56+ow), M = 100352 (= 784 * 128)
//   oc = output channel,    N = 256    (= 2 * 128)
//   k  = c*9 + r*3 + s,     K = 2304   (= 288 * 8)

#define CONV_N   32
#define CONV_C   256
#define CONV_HW  56
#define CONV_PIX (CONV_HW * CONV_HW)      // 3136
#define CONV_K   256
#define GEMM_K   (CONV_C * 9)             // 2304

#define TM 128
#define TN 128
#define TK 8
#define BS_PITCH (TN + 4)                 // 132: conflict-free loader stores

__device__ __forceinline__ void ffma2(unsigned long long& d,
                                      unsigned long long a,
                                      unsigned long long b) {
    asm("fma.rn.f32x2 %0, %1, %2, %0;" : "+l"(d) : "l"(a), "l"(b));
}
__device__ __forceinline__ unsigned long long bcast2(float v) {
    unsigned long long r;
    asm("mov.b64 %0, {%1, %1};" : "=l"(r) : "f"(v));
    return r;
}

__global__ __launch_bounds__(256, 2)
void conv3x3_igemm_kernel(const float* __restrict__ x,
                          const float* __restrict__ w,
                          float* __restrict__ out) {
    __shared__ float As[2][TK][TM];
    __shared__ float Bs[2][TK][BS_PITCH];

    const int tid     = threadIdx.x;
    const int block_m = blockIdx.x * TM;
    const int block_n = blockIdx.y * TN;

    // ---- A loader: 8k x 128p tile; 2 k-rows per pass, 4 passes
    const int a_p  = tid & 127;
    const int a_k0 = tid >> 7;            // 0..1
    const int p_glob_a = block_m + a_p;
    const int n_a  = p_glob_a / CONV_PIX;
    const int hw_a = p_glob_a - n_a * CONV_PIX;
    const int oh_a = hw_a / CONV_HW;
    const int ow_a = hw_a - oh_a * CONV_HW;
    const float* x_n = x + (size_t)n_a * CONV_C * CONV_PIX;

    // ---- B loader: k = tid%8, oc = tid/8, 4 passes
    const int b_k   = tid & 7;
    const int b_oc0 = tid >> 3;

    // ---- compute mapping: tx -> 4 pixel PAIRS at stride 32 (bank-conflict-free
    //      LDS.64: banks {2tx, 2tx+1} distinct across 16 threads); ty -> oc octet
    const int tx = tid & 15;
    const int ty = tid >> 4;

    // acc2[i][j]: oc i, pixel pair {2tx+32j, 2tx+32j+1}
    unsigned long long acc2[8][4];
    #pragma unroll
    for (int i = 0; i < 8; i++)
        #pragma unroll
        for (int j = 0; j < 4; j++) acc2[i][j] = 0ull;

    float a_reg[4], b_reg[4];

    // prologue: fetch tile 0 into buffer 0
    #pragma unroll
    for (int i = 0; i < 4; i++) {
        const int k = a_k0 + i * 2;
        const int c  = k / 9;
        const int rs = k - c * 9;
        const int r  = rs / 3;
        const int s  = rs - r * 3;
        const int ih = oh_a + r - 1, iw = ow_a + s - 1;
        const bool ok = ((unsigned)ih < CONV_HW) && ((unsigned)iw < CONV_HW);
        a_reg[i] = ok ? __ldg(&x_n[(c * CONV_HW + ih) * CONV_HW + iw]) : 0.f;
    }
    #pragma unroll
    for (int i = 0; i < 4; i++) {
        const int oc = block_n + b_oc0 + i * 32;
        b_reg[i] = __ldg(&w[(size_t)oc * GEMM_K + b_k]);
    }
    #pragma unroll
    for (int i = 0; i < 4; i++) As[0][a_k0 + i * 2][a_p] = a_reg[i];
    #pragma unroll
    for (int i = 0; i < 4; i++) Bs[0][b_k][b_oc0 + i * 32] = b_reg[i];
    __syncthreads();

    int buf = 0;
    for (int kt = 0; kt < GEMM_K; kt += TK) {
        const bool more = (kt + TK) < GEMM_K;
        if (more) {
            // prefetch next tile into registers (overlaps with compute below)
            #pragma unroll
            for (int i = 0; i < 4; i++) {
                const int k = kt + TK + a_k0 + i * 2;
                const int c  = k / 9;
                const int rs = k - c * 9;
                const int r  = rs / 3;
                const int s  = rs - r * 3;
                const int ih = oh_a + r - 1, iw = ow_a + s - 1;
                const bool ok = ((unsigned)ih < CONV_HW) && ((unsigned)iw < CONV_HW);
                a_reg[i] = ok ? __ldg(&x_n[(c * CONV_HW + ih) * CONV_HW + iw]) : 0.f;
            }
            #pragma unroll
            for (int i = 0; i < 4; i++) {
                const int oc = block_n + b_oc0 + i * 32;
                b_reg[i] = __ldg(&w[(size_t)oc * GEMM_K + kt + TK + b_k]);
            }
        }

        // compute current buffer: 32 FFMA2 per k-step
        #pragma unroll
        for (int kk = 0; kk < TK; kk++) {
            unsigned long long a2[4];
            #pragma unroll
            for (int j = 0; j < 4; j++)
                a2[j] = *reinterpret_cast<const unsigned long long*>(
                            &As[buf][kk][2 * tx + 32 * j]);

            const float4 b0 = *(const float4*)&Bs[buf][kk][ty * 8];
            const float4 b1 = *(const float4*)&Bs[buf][kk][ty * 8 + 4];
            float b[8];
            b[0]=b0.x; b[1]=b0.y; b[2]=b0.z; b[3]=b0.w;
            b[4]=b1.x; b[5]=b1.y; b[6]=b1.z; b[7]=b1.w;

            #pragma unroll
            for (int i = 0; i < 8; i++) {
                const unsigned long long bb = bcast2(b[i]);
                #pragma unroll
                for (int j = 0; j < 4; j++)
                    ffma2(acc2[i][j], bb, a2[j]);
            }
        }

        if (more) {
            // store into the ALTERNATE buffer — no race with readers of `buf`
            #pragma unroll
            for (int i = 0; i < 4; i++) As[buf ^ 1][a_k0 + i * 2][a_p] = a_reg[i];
            #pragma unroll
            for (int i = 0; i < 4; i++) Bs[buf ^ 1][b_k][b_oc0 + i * 32] = b_reg[i];
        }
        __syncthreads();        // single barrier per k-step
        buf ^= 1;
    }

    // ---- epilogue: per-pair stores (coalesced float2, 128B per warp phase)
    const int oc0 = block_n + ty * 8;
    #pragma unroll
    for (int j = 0; j < 4; j++) {
        const int p = block_m + 2 * tx + 32 * j;
        const int n  = p / CONV_PIX;
        const int hw = p - n * CONV_PIX;
        float* outp = out + (size_t)n * CONV_K * CONV_PIX + hw;
        #pragma unroll
        for (int i = 0; i < 8; i++) {
            float lo, hi;
            asm("mov.b64 {%0, %1}, %2;" : "=f"(lo), "=f"(hi) : "l"(acc2[i][j]));
            *(float2*)(outp + (size_t)(oc0 + i) * CONV_PIX) = make_float2(lo, hi);
        }
    }
}

extern "C" void kernel_launch(void* const* d_in, const int* in_sizes, int n_in,
                              void* d_out, int out_size) {
    const float* x = (const float*)d_in[0];   // [32,256,56,56]
    const float* w = (const float*)d_in[1];   // [256,256,3,3] == [256][2304]
    float* out = (float*)d_out;               // [32,256,56,56]

    dim3 grid( (CONV_N * CONV_PIX) / TM,      // 784
               CONV_K / TN );                 // 2
    conv3x3_igemm_kernel<<<grid, 256>>>(x, w, out);
}

// round 5
// speedup vs baseline: 2.5144x; 2.1166x over previous
#include <cuda_runtime.h>
#include <cuda_bf16.h>
#include <cstdint>

// Implicit-GEMM 3x3 conv via warp-level tensor-core MMA (mma.sync bf16),
// fp32 emulated with bf16 hi/lo 3-pass split:
//   D += Ah*Bh + Ah*Bl + Al*Bh   (fp32 accumulate in registers)
// GEMM: Out[p][oc] = sum_k A[p][k] * W2d[oc][k]
//   M = 100352 (784 x 128), N = 256 (2 x 128), K = 2304 (72 x 32)

#define CONV_HW  56
#define CONV_PIX 3136
#define CONV_K   256
#define GEMM_K   2304
#define BK       32
#define NCHUNK   (GEMM_K / BK)        // 72

#define PITCH    40                   // bf16 per smem row (80B): LDSM conflict-free
#define ROWB     (PITCH * 2)          // 80 bytes
#define A_BYTES  (128 * ROWB)         // 10240
#define OFF_AL   A_BYTES
#define OFF_BH   (2 * A_BYTES)
#define OFF_BL   (3 * A_BYTES)
#define STAGE    (4 * A_BYTES)        // 40960
#define SMEM_TOTAL (2 * STAGE)        // 81920

__device__ __forceinline__ uint32_t smem_u32(const void* p) {
    uint32_t a;
    asm("{ .reg .u64 t; cvta.to.shared.u64 t, %1; cvt.u32.u64 %0, t; }" : "=r"(a) : "l"(p));
    return a;
}

#define LDSM_X4(r0, r1, r2, r3, a) \
    asm volatile("ldmatrix.sync.aligned.m8n8.x4.shared.b16 {%0,%1,%2,%3}, [%4];" \
                 : "=r"(r0), "=r"(r1), "=r"(r2), "=r"(r3) : "r"(a))

#define MMA16816(c, a, b) \
    asm volatile("mma.sync.aligned.m16n8k16.row.col.f32.bf16.bf16.f32 " \
                 "{%0,%1,%2,%3}, {%4,%5,%6,%7}, {%8,%9}, {%0,%1,%2,%3};" \
                 : "+f"((c)[0]), "+f"((c)[1]), "+f"((c)[2]), "+f"((c)[3]) \
                 : "r"((a)[0]), "r"((a)[1]), "r"((a)[2]), "r"((a)[3]), \
                   "r"((b)[0]), "r"((b)[1]))

__device__ __forceinline__ uint32_t pack_hi(float v0, float v1) {
    __nv_bfloat162 h = __floats2bfloat162_rn(v0, v1);
    return *reinterpret_cast<uint32_t*>(&h);
}
__device__ __forceinline__ uint32_t pack_lo(float v0, float v1, uint32_t hi) {
    __nv_bfloat162 h = *reinterpret_cast<__nv_bfloat162*>(&hi);
    __nv_bfloat162 l = __floats2bfloat162_rn(v0 - __bfloat162float(h.x),
                                             v1 - __bfloat162float(h.y));
    return *reinterpret_cast<uint32_t*>(&l);
}

__global__ __launch_bounds__(256, 1)
void conv3x3_hmma_kernel(const float* __restrict__ x,
                         const float* __restrict__ w,
                         float* __restrict__ out) {
    extern __shared__ char smem[];
    const uint32_t sbase = smem_u32(smem);
    const int tid  = threadIdx.x;
    const int wrp  = tid >> 5;
    const int lane = tid & 31;

    const int block_m = blockIdx.x * 128;
    const int block_n = blockIdx.y * 128;

    // ---- A staging mapping: m = tid&127, k half = (tid>>7)*16 (16 k's each)
    const int a_m    = tid & 127;
    const int a_kh   = (tid >> 7) * 16;
    const int p_a    = block_m + a_m;
    const int nimg_a = p_a / CONV_PIX;
    const int hw_a   = p_a - nimg_a * CONV_PIX;
    const int oh     = hw_a / CONV_HW;
    const int ow     = hw_a - oh * CONV_HW;
    const float* x_n = x + (size_t)nimg_a * CONV_K * CONV_PIX;   // C == 256

    // ---- B staging mapping: kq = (tid&7)*4 floats, oc = (tid>>3) + 32p
    const int b_kq  = (tid & 7) * 4;
    const int b_oc0 = tid >> 3;

    // ---- warp tile: warp_m in {0,1} (64 rows), warp_n in {0..3} (32 cols)
    const int warp_m = wrp & 1;
    const int warp_n = wrp >> 1;
    const int m0 = warp_m * 64;
    const int n0 = warp_n * 32;

    // ldmatrix lane offsets (within-stage byte offsets, add stage base later)
    // A (m16k16): row = m0+mt*16+(lane&15), kb = 8*(lane>>4)
    const uint32_t a_lm_off = (uint32_t)(m0 + (lane & 15)) * ROWB + (uint32_t)(lane >> 4) * 16;
    // B (n16k16 pair): n = n0+nt2*16+(lane&7)+8*(lane>>4), kb = 8*((lane>>3)&1)
    const uint32_t b_lm_off = (uint32_t)(n0 + (lane & 7) + ((lane >> 4) << 3)) * ROWB
                            + (uint32_t)((lane >> 3) & 1) * 16;

    float acc[4][4][4];
    #pragma unroll
    for (int i = 0; i < 4; i++)
        #pragma unroll
        for (int j = 0; j < 4; j++)
            #pragma unroll
            for (int r = 0; r < 4; r++) acc[i][j][r] = 0.f;

    float av[16], bv[16];

    // ---------- staging load (gmem -> regs) ----------
    auto load_A = [&](int kt) {
        int k0 = kt + a_kh;
        int c  = k0 / 9;
        int rs = k0 - c * 9;
        int r  = rs / 3;
        int s  = rs - r * 3;
        const float* xc = x_n + c * CONV_PIX;
        #pragma unroll
        for (int j = 0; j < 16; j++) {
            const int ih = oh + r - 1, iw = ow + s - 1;
            const bool ok = ((unsigned)ih < CONV_HW) && ((unsigned)iw < CONV_HW);
            av[j] = ok ? __ldg(xc + ih * CONV_HW + iw) : 0.f;
            if (++s == 3) { s = 0; if (++r == 3) { r = 0; xc += CONV_PIX; } }
        }
    };
    auto load_B = [&](int kt) {
        #pragma unroll
        for (int p = 0; p < 4; p++) {
            const int oc = b_oc0 + p * 32;
            const float4 v = *(const float4*)(w + (size_t)(block_n + oc) * GEMM_K + kt + b_kq);
            bv[p * 4 + 0] = v.x; bv[p * 4 + 1] = v.y;
            bv[p * 4 + 2] = v.z; bv[p * 4 + 3] = v.w;
        }
    };
    // ---------- staging store (regs -> smem, split hi/lo) ----------
    auto store_stage = [&](char* st) {
        char* Ah = st;
        char* Al = st + OFF_AL;
        #pragma unroll
        for (int t = 0; t < 8; t++) {
            const uint32_t off = (uint32_t)a_m * ROWB + (uint32_t)(a_kh + 2 * t) * 2;
            const uint32_t hi = pack_hi(av[2 * t], av[2 * t + 1]);
            *(uint32_t*)(Ah + off) = hi;
            *(uint32_t*)(Al + off) = pack_lo(av[2 * t], av[2 * t + 1], hi);
        }
        char* Bh = st + OFF_BH;
        char* Bl = st + OFF_BL;
        #pragma unroll
        for (int p = 0; p < 4; p++) {
            const int oc = b_oc0 + p * 32;
            const uint32_t off = (uint32_t)oc * ROWB + (uint32_t)b_kq * 2;
            uint32_t h0 = pack_hi(bv[p*4+0], bv[p*4+1]);
            uint32_t h1 = pack_hi(bv[p*4+2], bv[p*4+3]);
            uint32_t l0 = pack_lo(bv[p*4+0], bv[p*4+1], h0);
            uint32_t l1 = pack_lo(bv[p*4+2], bv[p*4+3], h1);
            *(uint2*)(Bh + off) = make_uint2(h0, h1);
            *(uint2*)(Bl + off) = make_uint2(l0, l1);
        }
    };

    // prologue: stage chunk 0 into buffer 0
    load_A(0); load_B(0);
    store_stage(smem);
    __syncthreads();

    for (int c = 0; c < NCHUNK; ++c) {
        const int buf = c & 1;
        const uint32_t sstage = sbase + (uint32_t)buf * STAGE;
        const bool more = (c + 1) < NCHUNK;

        if (more) { load_A((c + 1) * BK); load_B((c + 1) * BK); }

        // ---- compute 2 k16 steps on current buffer ----
        #pragma unroll
        for (int ks = 0; ks < 2; ks++) {
            const uint32_t kso = (uint32_t)ks * 32;   // 16 bf16 = 32 bytes
            uint32_t a[4][4], b[2][4];

            // Bh
            LDSM_X4(b[0][0], b[0][1], b[0][2], b[0][3], sstage + OFF_BH + b_lm_off + kso);
            LDSM_X4(b[1][0], b[1][1], b[1][2], b[1][3], sstage + OFF_BH + b_lm_off + kso + 16 * ROWB);
            // Ah
            #pragma unroll
            for (int mt = 0; mt < 4; mt++)
                LDSM_X4(a[mt][0], a[mt][1], a[mt][2], a[mt][3],
                        sstage + a_lm_off + kso + (uint32_t)mt * 16 * ROWB);
            // Ah * Bh
            #pragma unroll
            for (int mt = 0; mt < 4; mt++)
                #pragma unroll
                for (int nt = 0; nt < 4; nt++)
                    MMA16816(acc[mt][nt], a[mt], &b[nt >> 1][(nt & 1) * 2]);
            // Bl
            LDSM_X4(b[0][0], b[0][1], b[0][2], b[0][3], sstage + OFF_BL + b_lm_off + kso);
            LDSM_X4(b[1][0], b[1][1], b[1][2], b[1][3], sstage + OFF_BL + b_lm_off + kso + 16 * ROWB);
            // Ah * Bl
            #pragma unroll
            for (int mt = 0; mt < 4; mt++)
                #pragma unroll
                for (int nt = 0; nt < 4; nt++)
                    MMA16816(acc[mt][nt], a[mt], &b[nt >> 1][(nt & 1) * 2]);
            // Bh again (cheap reload), Al
            LDSM_X4(b[0][0], b[0][1], b[0][2], b[0][3], sstage + OFF_BH + b_lm_off + kso);
            LDSM_X4(b[1][0], b[1][1], b[1][2], b[1][3], sstage + OFF_BH + b_lm_off + kso + 16 * ROWB);
            #pragma unroll
            for (int mt = 0; mt < 4; mt++)
                LDSM_X4(a[mt][0], a[mt][1], a[mt][2], a[mt][3],
                        sstage + OFF_AL + a_lm_off + kso + (uint32_t)mt * 16 * ROWB);
            // Al * Bh
            #pragma unroll
            for (int mt = 0; mt < 4; mt++)
                #pragma unroll
                for (int nt = 0; nt < 4; nt++)
                    MMA16816(acc[mt][nt], a[mt], &b[nt >> 1][(nt & 1) * 2]);
        }

        if (more) store_stage(smem + (buf ^ 1) * STAGE);
        __syncthreads();
    }

    // ---- epilogue: c-frag scatter (pairs along oc planes, octets along pixels)
    const int oc_base = block_n + n0 + (lane & 3) * 2;
    #pragma unroll
    for (int mt = 0; mt < 4; mt++) {
        const int p_lo = block_m + m0 + mt * 16 + (lane >> 2);
        const int p_hi = p_lo + 8;
        const int nl = p_lo / CONV_PIX, hl = p_lo - nl * CONV_PIX;
        const int nh = p_hi / CONV_PIX, hh = p_hi - nh * CONV_PIX;
        float* olo = out + (size_t)nl * CONV_K * CONV_PIX + hl;
        float* ohi = out + (size_t)nh * CONV_K * CONV_PIX + hh;
        #pragma unroll
        for (int nt = 0; nt < 4; nt++) {
            const int oc = oc_base + nt * 8;
            olo[(size_t)(oc    ) * CONV_PIX] = acc[mt][nt][0];
            olo[(size_t)(oc + 1) * CONV_PIX] = acc[mt][nt][1];
            ohi[(size_t)(oc    ) * CONV_PIX] = acc[mt][nt][2];
            ohi[(size_t)(oc + 1) * CONV_PIX] = acc[mt][nt][3];
        }
    }
}

extern "C" void kernel_launch(void* const* d_in, const int* in_sizes, int n_in,
                              void* d_out, int out_size) {
    const float* x = (const float*)d_in[0];   // [32,256,56,56]
    const float* w = (const float*)d_in[1];   // [256,256,3,3] == [256][2304]
    float* out = (float*)d_out;               // [32,256,56,56]

    cudaFuncSetAttribute(conv3x3_hmma_kernel,
                         cudaFuncAttributeMaxDynamicSharedMemorySize, SMEM_TOTAL);
    dim3 grid(784, 2);
    conv3x3_hmma_kernel<<<grid, 256, SMEM_TOTAL>>>(x, w, out);
}

// round 6
// speedup vs baseline: 2.5809x; 1.0265x over previous
#include <cuda_runtime.h>
#include <cuda_bf16.h>
#include <cstdint>

// Implicit-GEMM 3x3 conv via warp-level bf16 mma.sync, fp32 via hi/lo split:
//   D += Ah*Bh + Ah*Bl + Al*Bh  (fp32 accumulators)
// Split precomputed by prep kernels into __device__ scratch:
//   g_xs : interleaved hi16|lo16 per x element  (same indexing as x)
//   g_wh / g_wl : planar bf16 weight tensors [256][2304]

#define CONV_HW  56
#define CONV_PIX 3136
#define CONV_K   256
#define GEMM_K   2304
#define X_ELEMS  (32 * 256 * CONV_PIX)     // 25,690,112
#define W_ELEMS  (CONV_K * GEMM_K)         // 589,824
#define BK       32
#define NCHUNK   (GEMM_K / BK)             // 72

#define PITCH    40                        // bf16 per smem row (80B), LDSM conflict-free
#define ROWB     (PITCH * 2)
#define A_BYTES  (128 * ROWB)              // 10240
#define OFF_AL   A_BYTES
#define OFF_BH   (2 * A_BYTES)
#define OFF_BL   (3 * A_BYTES)
#define STAGE    (4 * A_BYTES)             // 40960
#define SMEM_TOTAL (2 * STAGE)             // 81920

__device__ uint32_t      g_xs[X_ELEMS];    // hi | lo<<16
__device__ __nv_bfloat16 g_wh[W_ELEMS];
__device__ __nv_bfloat16 g_wl[W_ELEMS];

__device__ __forceinline__ uint32_t smem_u32(const void* p) {
    uint32_t a;
    asm("{ .reg .u64 t; cvta.to.shared.u64 t, %1; cvt.u32.u64 %0, t; }" : "=r"(a) : "l"(p));
    return a;
}
__device__ __forceinline__ uint32_t prmt(uint32_t a, uint32_t b, uint32_t sel) {
    uint32_t r;
    asm("prmt.b32 %0, %1, %2, %3;" : "=r"(r) : "r"(a), "r"(b), "r"(sel));
    return r;
}

#define LDSM_X4(r0, r1, r2, r3, a) \
    asm volatile("ldmatrix.sync.aligned.m8n8.x4.shared.b16 {%0,%1,%2,%3}, [%4];" \
                 : "=r"(r0), "=r"(r1), "=r"(r2), "=r"(r3) : "r"(a))

#define MMA16816(c, a, b) \
    asm volatile("mma.sync.aligned.m16n8k16.row.col.f32.bf16.bf16.f32 " \
                 "{%0,%1,%2,%3}, {%4,%5,%6,%7}, {%8,%9}, {%0,%1,%2,%3};" \
                 : "+f"((c)[0]), "+f"((c)[1]), "+f"((c)[2]), "+f"((c)[3]) \
                 : "r"((a)[0]), "r"((a)[1]), "r"((a)[2]), "r"((a)[3]), \
                   "r"((b)[0]), "r"((b)[1]))

// ---------------- prep kernels ----------------

__global__ void split_x_kernel(const float* __restrict__ x) {
    const int i4 = blockIdx.x * blockDim.x + threadIdx.x;
    if (i4 * 4 >= X_ELEMS) return;
    const float4 v = *(const float4*)(x + (size_t)i4 * 4);
    uint4 o;
    const float vv[4] = {v.x, v.y, v.z, v.w};
    uint32_t r[4];
    #pragma unroll
    for (int j = 0; j < 4; j++) {
        __nv_bfloat16 h = __float2bfloat16(vv[j]);
        __nv_bfloat16 l = __float2bfloat16(vv[j] - __bfloat162float(h));
        r[j] = (uint32_t)*reinterpret_cast<uint16_t*>(&h)
             | ((uint32_t)*reinterpret_cast<uint16_t*>(&l) << 16);
    }
    o.x = r[0]; o.y = r[1]; o.z = r[2]; o.w = r[3];
    *(uint4*)(g_xs + (size_t)i4 * 4) = o;
}

__global__ void split_w_kernel(const float* __restrict__ w) {
    const int i = blockIdx.x * blockDim.x + threadIdx.x;
    if (i >= W_ELEMS) return;
    const float v = w[i];
    __nv_bfloat16 h = __float2bfloat16(v);
    __nv_bfloat16 l = __float2bfloat16(v - __bfloat162float(h));
    g_wh[i] = h;
    g_wl[i] = l;
}

// ---------------- main kernel ----------------

__global__ __launch_bounds__(512, 1)
void conv3x3_hmma_kernel(float* __restrict__ out, int block_n_sel) {
    extern __shared__ char smem[];
    const uint32_t sbase = smem_u32(smem);
    const int tid  = threadIdx.x;
    const int wrp  = tid >> 5;
    const int lane = tid & 31;

    const int block_m = blockIdx.x * 128;
    const int block_n = blockIdx.y * 128;

    // ---- A staging mapping: m = tid&127, k group = (tid>>7)*8 (8 k's each)
    const int a_m  = tid & 127;
    const int a_kg = (tid >> 7) * 8;
    const int p_a    = block_m + a_m;
    const int nimg_a = p_a / CONV_PIX;
    const int hw_a   = p_a - nimg_a * CONV_PIX;
    const int oh     = hw_a / CONV_HW;
    const int ow     = hw_a - oh * CONV_HW;
    const uint32_t* xs_n = g_xs + (size_t)nimg_a * CONV_K * CONV_PIX;

    // ---- B staging mapping: oc = tid>>2, quad = tid&3 (16B each of Bh and Bl)
    const int b_oc = tid >> 2;
    const int b_q  = tid & 3;
    const __nv_bfloat16* whp = g_wh + (size_t)(block_n + b_oc) * GEMM_K + b_q * 8;
    const __nv_bfloat16* wlp = g_wl + (size_t)(block_n + b_oc) * GEMM_K + b_q * 8;

    // ---- warp tile: 32x32; warp_m = wrp&3, warp_n = wrp>>2
    const int m0 = (wrp & 3) * 32;
    const int n0 = (wrp >> 2) * 32;

    const uint32_t a_lm_off = (uint32_t)(m0 + (lane & 15)) * ROWB + (uint32_t)(lane >> 4) * 16;
    const uint32_t b_lm_off = (uint32_t)(n0 + (lane & 7) + ((lane >> 4) << 3)) * ROWB
                            + (uint32_t)((lane >> 3) & 1) * 16;

    float acc[2][4][4];
    #pragma unroll
    for (int i = 0; i < 2; i++)
        #pragma unroll
        for (int j = 0; j < 4; j++)
            #pragma unroll
            for (int r = 0; r < 4; r++) acc[i][j][r] = 0.f;

    uint32_t axv[8];        // interleaved hi|lo for 8 k's
    uint4    bhv, blv;      // B copies (8 bf16 each)

    auto load_stage = [&](int kt) {
        // A: 8 k's for (m, kg)
        int k0 = kt + a_kg;
        int c  = k0 / 9;
        int rs = k0 - c * 9;
        int r  = rs / 3;
        int s  = rs - r * 3;
        const uint32_t* xc = xs_n + c * CONV_PIX;
        #pragma unroll
        for (int j = 0; j < 8; j++) {
            const int ih = oh + r - 1, iw = ow + s - 1;
            const bool ok = ((unsigned)ih < CONV_HW) && ((unsigned)iw < CONV_HW);
            axv[j] = ok ? __ldg(xc + ih * CONV_HW + iw) : 0u;
            if (++s == 3) { s = 0; if (++r == 3) { r = 0; xc += CONV_PIX; } }
        }
        // B: 16B of Bh and Bl
        bhv = *(const uint4*)(whp + kt);
        blv = *(const uint4*)(wlp + kt);
    };
    auto store_stage = [&](char* st) {
        char* Ah = st;
        char* Al = st + OFF_AL;
        #pragma unroll
        for (int t = 0; t < 4; t++) {
            const uint32_t off = (uint32_t)a_m * ROWB + (uint32_t)(a_kg + 2 * t) * 2;
            *(uint32_t*)(Ah + off) = prmt(axv[2*t], axv[2*t+1], 0x5410);  // hi pair
            *(uint32_t*)(Al + off) = prmt(axv[2*t], axv[2*t+1], 0x7632);  // lo pair
        }
        const uint32_t boff = (uint32_t)b_oc * ROWB + (uint32_t)b_q * 16;
        *(uint4*)(st + OFF_BH + boff) = bhv;
        *(uint4*)(st + OFF_BL + boff) = blv;
    };

    load_stage(0);
    store_stage(smem);
    __syncthreads();

    for (int c = 0; c < NCHUNK; ++c) {
        const int buf = c & 1;
        const uint32_t sstage = sbase + (uint32_t)buf * STAGE;
        const bool more = (c + 1) < NCHUNK;

        if (more) load_stage((c + 1) * BK);

        #pragma unroll
        for (int ks = 0; ks < 2; ks++) {
            const uint32_t kso = (uint32_t)ks * 32;
            uint32_t a[2][4], bh[2][4], bl[2][4];

            LDSM_X4(bh[0][0], bh[0][1], bh[0][2], bh[0][3], sstage + OFF_BH + b_lm_off + kso);
            LDSM_X4(bh[1][0], bh[1][1], bh[1][2], bh[1][3], sstage + OFF_BH + b_lm_off + kso + 16 * ROWB);
            #pragma unroll
            for (int mt = 0; mt < 2; mt++)
                LDSM_X4(a[mt][0], a[mt][1], a[mt][2], a[mt][3],
                        sstage + a_lm_off + kso + (uint32_t)mt * 16 * ROWB);
            // Ah * Bh
            #pragma unroll
            for (int mt = 0; mt < 2; mt++)
                #pragma unroll
                for (int nt = 0; nt < 4; nt++)
                    MMA16816(acc[mt][nt], a[mt], &bh[nt >> 1][(nt & 1) * 2]);
            // Ah * Bl
            LDSM_X4(bl[0][0], bl[0][1], bl[0][2], bl[0][3], sstage + OFF_BL + b_lm_off + kso);
            LDSM_X4(bl[1][0], bl[1][1], bl[1][2], bl[1][3], sstage + OFF_BL + b_lm_off + kso + 16 * ROWB);
            #pragma unroll
            for (int mt = 0; mt < 2; mt++)
                #pragma unroll
                for (int nt = 0; nt < 4; nt++)
                    MMA16816(acc[mt][nt], a[mt], &bl[nt >> 1][(nt & 1) * 2]);
            // Al * Bh  (bh still live in registers)
            #pragma unroll
            for (int mt = 0; mt < 2; mt++)
                LDSM_X4(a[mt][0], a[mt][1], a[mt][2], a[mt][3],
                        sstage + OFF_AL + a_lm_off + kso + (uint32_t)mt * 16 * ROWB);
            #pragma unroll
            for (int mt = 0; mt < 2; mt++)
                #pragma unroll
                for (int nt = 0; nt < 4; nt++)
                    MMA16816(acc[mt][nt], a[mt], &bh[nt >> 1][(nt & 1) * 2]);
        }

        if (more) store_stage(smem + (buf ^ 1) * STAGE);
        __syncthreads();
    }

    // ---- epilogue
    const int oc_base = block_n + n0 + (lane & 3) * 2;
    #pragma unroll
    for (int mt = 0; mt < 2; mt++) {
        const int p_lo = block_m + m0 + mt * 16 + (lane >> 2);
        const int p_hi = p_lo + 8;
        const int nl = p_lo / CONV_PIX, hl = p_lo - nl * CONV_PIX;
        const int nh = p_hi / CONV_PIX, hh = p_hi - nh * CONV_PIX;
        float* olo = out + (size_t)nl * CONV_K * CONV_PIX + hl;
        float* ohi = out + (size_t)nh * CONV_K * CONV_PIX + hh;
        #pragma unroll
        for (int nt = 0; nt < 4; nt++) {
            const int oc = oc_base + nt * 8;
            olo[(size_t)(oc    ) * CONV_PIX] = acc[mt][nt][0];
            olo[(size_t)(oc + 1) * CONV_PIX] = acc[mt][nt][1];
            ohi[(size_t)(oc    ) * CONV_PIX] = acc[mt][nt][2];
            ohi[(size_t)(oc + 1) * CONV_PIX] = acc[mt][nt][3];
        }
    }
}

extern "C" void kernel_launch(void* const* d_in, const int* in_sizes, int n_in,
                              void* d_out, int out_size) {
    const float* x = (const float*)d_in[0];   // [32,256,56,56]
    const float* w = (const float*)d_in[1];   // [256,256,3,3] == [256][2304]
    float* out = (float*)d_out;

    split_x_kernel<<<(X_ELEMS / 4 + 255) / 256, 256>>>(x);
    split_w_kernel<<<(W_ELEMS + 255) / 256, 256>>>(w);

    cudaFuncSetAttribute(conv3x3_hmma_kernel,
                         cudaFuncAttributeMaxDynamicSharedMemorySize, SMEM_TOTAL);
    dim3 grid(784, 2);
    conv3x3_hmma_kernel<<<grid, 512, SMEM_TOTAL>>>(out, 0);
}

// round 7
// speedup vs baseline: 2.8398x; 1.1003x over previous
#include <cuda_runtime.h>
#include <cuda_bf16.h>
#include <cstdint>

// Implicit-GEMM 3x3 conv via warp-level bf16 mma.sync, fp32 via hi/lo split:
//   D += Ah*Bh + Ah*Bl + Al*Bh  (fp32 accumulators)
// Hi/lo split precomputed into __device__ scratch; main loop software-pipelines
// ldmatrix fragment loads against MMA passes to overlap crossbar + tensor pipes.

#define CONV_HW  56
#define CONV_PIX 3136
#define CONV_K   256
#define GEMM_K   2304
#define X_ELEMS  (32 * 256 * CONV_PIX)
#define W_ELEMS  (CONV_K * GEMM_K)
#define BK       32
#define NCHUNK   (GEMM_K / BK)             // 72

#define PITCH    40                        // bf16 per smem row (80B), LDSM conflict-free
#define ROWB     (PITCH * 2)
#define A_BYTES  (128 * ROWB)              // 10240
#define OFF_AL   A_BYTES
#define OFF_BH   (2 * A_BYTES)
#define OFF_BL   (3 * A_BYTES)
#define STAGE    (4 * A_BYTES)             // 40960
#define SMEM_TOTAL (2 * STAGE)             // 81920

__device__ uint32_t      g_xs[X_ELEMS];    // hi | lo<<16
__device__ __nv_bfloat16 g_wh[W_ELEMS];
__device__ __nv_bfloat16 g_wl[W_ELEMS];

__device__ __forceinline__ uint32_t smem_u32(const void* p) {
    uint32_t a;
    asm("{ .reg .u64 t; cvta.to.shared.u64 t, %1; cvt.u32.u64 %0, t; }" : "=r"(a) : "l"(p));
    return a;
}
__device__ __forceinline__ uint32_t prmt(uint32_t a, uint32_t b, uint32_t sel) {
    uint32_t r;
    asm("prmt.b32 %0, %1, %2, %3;" : "=r"(r) : "r"(a), "r"(b), "r"(sel));
    return r;
}

#define LDSM_X4(r0, r1, r2, r3, a) \
    asm volatile("ldmatrix.sync.aligned.m8n8.x4.shared.b16 {%0,%1,%2,%3}, [%4];" \
                 : "=r"(r0), "=r"(r1), "=r"(r2), "=r"(r3) : "r"(a))

#define MMA16816(c, a, b) \
    asm volatile("mma.sync.aligned.m16n8k16.row.col.f32.bf16.bf16.f32 " \
                 "{%0,%1,%2,%3}, {%4,%5,%6,%7}, {%8,%9}, {%0,%1,%2,%3};" \
                 : "+f"((c)[0]), "+f"((c)[1]), "+f"((c)[2]), "+f"((c)[3]) \
                 : "r"((a)[0]), "r"((a)[1]), "r"((a)[2]), "r"((a)[3]), \
                   "r"((b)[0]), "r"((b)[1]))

// ---------------- prep kernels ----------------

__global__ void split_x_kernel(const float* __restrict__ x) {
    const int i4 = blockIdx.x * blockDim.x + threadIdx.x;
    if (i4 * 4 >= X_ELEMS) return;
    const float4 v = *(const float4*)(x + (size_t)i4 * 4);
    const float vv[4] = {v.x, v.y, v.z, v.w};
    uint32_t r[4];
    #pragma unroll
    for (int j = 0; j < 4; j++) {
        __nv_bfloat16 h = __float2bfloat16(vv[j]);
        __nv_bfloat16 l = __float2bfloat16(vv[j] - __bfloat162float(h));
        r[j] = (uint32_t)*reinterpret_cast<uint16_t*>(&h)
             | ((uint32_t)*reinterpret_cast<uint16_t*>(&l) << 16);
    }
    *(uint4*)(g_xs + (size_t)i4 * 4) = make_uint4(r[0], r[1], r[2], r[3]);
}

__global__ void split_w_kernel(const float* __restrict__ w) {
    const int i = blockIdx.x * blockDim.x + threadIdx.x;
    if (i >= W_ELEMS) return;
    const float v = w[i];
    __nv_bfloat16 h = __float2bfloat16(v);
    __nv_bfloat16 l = __float2bfloat16(v - __bfloat162float(h));
    g_wh[i] = h;
    g_wl[i] = l;
}

// ---------------- main kernel ----------------

__global__ __launch_bounds__(512, 1)
void conv3x3_hmma_kernel(float* __restrict__ out) {
    extern __shared__ char smem[];
    const uint32_t sbase = smem_u32(smem);
    const int tid  = threadIdx.x;
    const int wrp  = tid >> 5;
    const int lane = tid & 31;

    const int block_m = blockIdx.x * 128;
    const int block_n = blockIdx.y * 128;

    // ---- A staging mapping: m = tid&127, k group = (tid>>7)*8
    const int a_m  = tid & 127;
    const int a_kg = (tid >> 7) * 8;
    const int p_a    = block_m + a_m;
    const int nimg_a = p_a / CONV_PIX;
    const int hw_a   = p_a - nimg_a * CONV_PIX;
    const int oh     = hw_a / CONV_HW;
    const int ow     = hw_a - oh * CONV_HW;
    const uint32_t* xs_n = g_xs + (size_t)nimg_a * CONV_K * CONV_PIX;

    // ---- B staging mapping: oc = tid>>2, quad = tid&3
    const int b_oc = tid >> 2;
    const int b_q  = tid & 3;
    const __nv_bfloat16* whp = g_wh + (size_t)(block_n + b_oc) * GEMM_K + b_q * 8;
    const __nv_bfloat16* wlp = g_wl + (size_t)(block_n + b_oc) * GEMM_K + b_q * 8;

    // ---- warp tile 32x32: warp_m = wrp&3, warp_n = wrp>>2
    const int m0 = (wrp & 3) * 32;
    const int n0 = (wrp >> 2) * 32;

    const uint32_t a_lm_off = (uint32_t)(m0 + (lane & 15)) * ROWB + (uint32_t)(lane >> 4) * 16;
    const uint32_t b_lm_off = (uint32_t)(n0 + (lane & 7) + ((lane >> 4) << 3)) * ROWB
                            + (uint32_t)((lane >> 3) & 1) * 16;

    float acc[2][4][4];
    #pragma unroll
    for (int i = 0; i < 2; i++)
        #pragma unroll
        for (int j = 0; j < 4; j++)
            #pragma unroll
            for (int r = 0; r < 4; r++) acc[i][j][r] = 0.f;

    uint32_t axv[8];
    uint4    bhv, blv;

    auto load_stage = [&](int kt) {
        int k0 = kt + a_kg;
        int c  = k0 / 9;
        int rs = k0 - c * 9;
        int r  = rs / 3;
        int s  = rs - r * 3;
        const uint32_t* xc = xs_n + c * CONV_PIX;
        #pragma unroll
        for (int j = 0; j < 8; j++) {
            const int ih = oh + r - 1, iw = ow + s - 1;
            const bool ok = ((unsigned)ih < CONV_HW) && ((unsigned)iw < CONV_HW);
            axv[j] = ok ? __ldg(xc + ih * CONV_HW + iw) : 0u;
            if (++s == 3) { s = 0; if (++r == 3) { r = 0; xc += CONV_PIX; } }
        }
        bhv = *(const uint4*)(whp + kt);
        blv = *(const uint4*)(wlp + kt);
    };
    auto store_stage = [&](char* st) {
        char* Ah = st;
        char* Al = st + OFF_AL;
        #pragma unroll
        for (int t = 0; t < 4; t++) {
            const uint32_t off = (uint32_t)a_m * ROWB + (uint32_t)(a_kg + 2 * t) * 2;
            *(uint32_t*)(Ah + off) = prmt(axv[2*t], axv[2*t+1], 0x5410);
            *(uint32_t*)(Al + off) = prmt(axv[2*t], axv[2*t+1], 0x7632);
        }
        const uint32_t boff = (uint32_t)b_oc * ROWB + (uint32_t)b_q * 16;
        *(uint4*)(st + OFF_BH + boff) = bhv;
        *(uint4*)(st + OFF_BL + boff) = blv;
    };

    // frag load helpers
    auto ldA2 = [&](uint32_t sstage, uint32_t base, uint32_t kso, uint32_t (&a)[2][4]) {
        #pragma unroll
        for (int mt = 0; mt < 2; mt++)
            LDSM_X4(a[mt][0], a[mt][1], a[mt][2], a[mt][3],
                    sstage + base + a_lm_off + kso + (uint32_t)mt * 16 * ROWB);
    };
    auto ldB2 = [&](uint32_t sstage, uint32_t base, uint32_t kso, uint32_t (&b)[2][4]) {
        LDSM_X4(b[0][0], b[0][1], b[0][2], b[0][3], sstage + base + b_lm_off + kso);
        LDSM_X4(b[1][0], b[1][1], b[1][2], b[1][3], sstage + base + b_lm_off + kso + 16 * ROWB);
    };
    auto mma_pass = [&](uint32_t (&a)[2][4], uint32_t (&b)[2][4]) {
        #pragma unroll
        for (int mt = 0; mt < 2; mt++)
            #pragma unroll
            for (int nt = 0; nt < 4; nt++)
                MMA16816(acc[mt][nt], a[mt], &b[nt >> 1][(nt & 1) * 2]);
    };

    load_stage(0);
    store_stage(smem);
    __syncthreads();

    for (int c = 0; c < NCHUNK; ++c) {
        const int buf = c & 1;
        const uint32_t sstage = sbase + (uint32_t)buf * STAGE;
        const bool more = (c + 1) < NCHUNK;

        if (more) load_stage((c + 1) * BK);   // global prefetch (long latency)

        // ---- pipelined 6-stage schedule over (ks, pass) ----
        uint32_t ah0[2][4], al0[2][4], bh0[2][4], bl0[2][4];
        uint32_t ah1[2][4], al1[2][4], bh1[2][4], bl1[2][4];

        ldB2(sstage, OFF_BH, 0, bh0);
        ldA2(sstage, 0,      0, ah0);
        ldB2(sstage, OFF_BL, 0, bl0);         // prefetch pass-2 frags
        mma_pass(ah0, bh0);                   // pass 1 (ks0): Ah*Bh
        ldA2(sstage, OFF_AL, 0, al0);         // prefetch pass-3 frags
        mma_pass(ah0, bl0);                   // pass 2 (ks0): Ah*Bl
        ldB2(sstage, OFF_BH, 32, bh1);        // prefetch ks1 frags
        ldA2(sstage, 0,      32, ah1);
        mma_pass(al0, bh0);                   // pass 3 (ks0): Al*Bh
        ldB2(sstage, OFF_BL, 32, bl1);
        mma_pass(ah1, bh1);                   // pass 1 (ks1)
        ldA2(sstage, OFF_AL, 32, al1);
        if (more) store_stage(smem + (buf ^ 1) * STAGE);  // STS overlaps last passes
        mma_pass(ah1, bl1);                   // pass 2 (ks1)
        mma_pass(al1, bh1);                   // pass 3 (ks1)

        __syncthreads();
    }

    // ---- epilogue
    const int oc_base = block_n + n0 + (lane & 3) * 2;
    #pragma unroll
    for (int mt = 0; mt < 2; mt++) {
        const int p_lo = block_m + m0 + mt * 16 + (lane >> 2);
        const int p_hi = p_lo + 8;
        const int nl = p_lo / CONV_PIX, hl = p_lo - nl * CONV_PIX;
        const int nh = p_hi / CONV_PIX, hh = p_hi - nh * CONV_PIX;
        float* olo = out + (size_t)nl * CONV_K * CONV_PIX + hl;
        float* ohi = out + (size_t)nh * CONV_K * CONV_PIX + hh;
        #pragma unroll
        for (int nt = 0; nt < 4; nt++) {
            const int oc = oc_base + nt * 8;
            olo[(size_t)(oc    ) * CONV_PIX] = acc[mt][nt][0];
            olo[(size_t)(oc + 1) * CONV_PIX] = acc[mt][nt][1];
            ohi[(size_t)(oc    ) * CONV_PIX] = acc[mt][nt][2];
            ohi[(size_t)(oc + 1) * CONV_PIX] = acc[mt][nt][3];
        }
    }
}

extern "C" void kernel_launch(void* const* d_in, const int* in_sizes, int n_in,
                              void* d_out, int out_size) {
    const float* x = (const float*)d_in[0];
    const float* w = (const float*)d_in[1];
    float* out = (float*)d_out;

    split_x_kernel<<<(X_ELEMS / 4 + 255) / 256, 256>>>(x);
    split_w_kernel<<<(W_ELEMS + 255) / 256, 256>>>(w);

    cudaFuncSetAttribute(conv3x3_hmma_kernel,
                         cudaFuncAttributeMaxDynamicSharedMemorySize, SMEM_TOTAL);
    dim3 grid(784, 2);
    conv3x3_hmma_kernel<<<grid, 512, SMEM_TOTAL>>>(out);
}